// round 15
// baseline (speedup 1.0000x reference)
#include <cuda_runtime.h>
#include <cuda_fp16.h>
#include <math.h>
#include <stdint.h>

#define NTOK  65536
#define IN_F  64
#define OUT_F 64
#define RAD_F 32
#define ANG_F 16
#define HID   64

#define TILE_M   128
#define NTILES   (NTOK / TILE_M)   // 512
#define THREADS  256

#define APITCH   144               // fp16 tile pitch (ldsm conflict-free)

// ---------------------------------------------------------------------------
// B stream in FRAGMENT order (validated R13/R14):
// addr(slot, nh, ks, row16, lane, j, byte) =
//   (slot*2+nh)*4096 + (ks*2+row16)*512 + lane*16 + j*4 + byte*2
// Slots 0..63 = W2_i, slot 64 = b2, slot 65 = padding.
// Per (slot, nh): 4096 contiguous bytes = 32 lanes x 128B lines.
// ---------------------------------------------------------------------------
__device__ __align__(1024) uint8_t g_streamR[(size_t)66 * 8192];

__device__ __forceinline__ void store_frag(int slot, int o, int k, __half v) {
    const int nh    = o >> 5;
    const int ol    = o & 31;
    const int row16 = ol >> 4;
    const int oo    = ol & 15;
    const int ks    = k >> 4;
    const int kl    = k & 15;
    const int j     = (oo >> 3) * 2 + (kl >> 3);
    const int lane  = (oo & 7) * 4 + ((kl & 7) >> 1);
    const int byte  = kl & 1;
    const size_t addr = (size_t)(slot * 2 + nh) * 4096
                      + (size_t)(ks * 2 + row16) * 512
                      + (size_t)lane * 16 + j * 4 + byte * 2;
    *(__half*)(g_streamR + addr) = v;
}

__global__ void tp_wsplit(const float* __restrict__ W2, const float* __restrict__ b2)
{
    const int idx = blockIdx.x * THREADS + threadIdx.x;
    if (idx < 64 * 4096) {
        const int k  = idx >> 12;
        const int io = idx & 4095;
        const int o  = io & 63;
        const int i  = io >> 6;
        store_frag(i, o, k, __float2half_rn(W2[idx]));
    } else if (idx < 64 * 4096 + 4096) {
        const int e = idx - 64 * 4096;
        const int i = e >> 6;     // contraction dim of the b2 pass
        const int o = e & 63;
        store_frag(64, o, i, __float2half_rn(b2[e]));
    }
}

// ---------------------------------------------------------------------------
// PTX helpers
// ---------------------------------------------------------------------------
__device__ __forceinline__ void ldsm_x4(uint32_t* r, uint32_t addr) {
    asm volatile("ldmatrix.sync.aligned.m8n8.x4.shared.b16 {%0,%1,%2,%3}, [%4];"
        : "=r"(r[0]), "=r"(r[1]), "=r"(r[2]), "=r"(r[3]) : "r"(addr));
}
__device__ __forceinline__ void mma_f16(float* d, const uint32_t* a,
                                        uint32_t b0, uint32_t b1) {
    asm volatile(
        "mma.sync.aligned.m16n8k16.row.col.f32.f16.f16.f32 "
        "{%0,%1,%2,%3}, {%4,%5,%6,%7}, {%8,%9}, {%0,%1,%2,%3};"
        : "+f"(d[0]), "+f"(d[1]), "+f"(d[2]), "+f"(d[3])
        : "r"(a[0]), "r"(a[1]), "r"(a[2]), "r"(a[3]), "r"(b0), "r"(b1));
}
__device__ __forceinline__ uint32_t hmul2u(uint32_t a, uint32_t f) {
    uint32_t d;
    asm("mul.rn.f16x2 %0, %1, %2;" : "=r"(d) : "r"(a), "r"(f));
    return d;
}
__device__ __forceinline__ uint32_t lds32(uint32_t addr) {
    uint32_t v;
    asm volatile("ld.shared.b32 %0, [%1];" : "=r"(v) : "r"(addr));
    return v;
}
__device__ __forceinline__ void prefetch_l1(const void* p) {
    asm volatile("prefetch.global.L1 [%0];" :: "l"(p));
}
__device__ __forceinline__ float silu_tanh(float x) {
    float t;
    asm("tanh.approx.f32 %0, %1;" : "=f"(t) : "f"(0.5f * x));
    const float hx = 0.5f * x;
    return fmaf(hx, t, hx);
}

// ---------------------------------------------------------------------------
// SMEM layout (bytes) — 49664 total
// ---------------------------------------------------------------------------
#define SM_A    0u        // h fp16 tile 128 rows          (18432)
#define SM_F    18432u    // radial staging, then f fp16   (18432)
#define SM_W1   36864u    // W1 fp32 [32][64]              (8192)
#define SM_WA   45056u    // Wa fp32 [16][64]              (4096)
#define SM_B1   49152u    // b1 fp32 [64]                  (256)
#define SM_BA   49408u    // ba fp32 [64]                  (256)
#define SMEM_BYTES 49664

// ---------------------------------------------------------------------------
// Main kernel: 128 tokens/CTA, 8 warps, 2 CTAs/SM.
// Warp = (m-pair, n-half): 32 rows x 32 cols. B via LDG fragments with
// distance-1 register pipeline + distance-2-slot L1 prefetch; no barriers.
// ---------------------------------------------------------------------------
__global__ __launch_bounds__(THREADS, 2)
void tp_main(const float* __restrict__ features,
             const float* __restrict__ radial,
             const float* __restrict__ angular,
             const float* __restrict__ W1,
             const float* __restrict__ b1,
             const float* __restrict__ Wa,
             const float* __restrict__ ba,
             float* __restrict__ out)
{
    extern __shared__ __align__(1024) uint8_t smem[];
    const uint32_t sb = (uint32_t)__cvta_generic_to_shared(smem);
    const int tid  = threadIdx.x;
    const int lane = tid & 31;
    const int warp = tid >> 5;
    const int n0   = blockIdx.x * TILE_M;

    // ---- stage radial (into SM_F region) + weights ----
    float* srad = (float*)(smem + SM_F);     // [128][33]
    float* sW1  = (float*)(smem + SM_W1);
    float* sWa  = (float*)(smem + SM_WA);
    float* sb1_ = (float*)(smem + SM_B1);
    float* sba_ = (float*)(smem + SM_BA);

    for (int e = tid; e < TILE_M * RAD_F; e += THREADS) {
        const int m = e >> 5, r = e & 31;
        srad[m * 33 + r] = radial[(size_t)(n0 + m) * RAD_F + r];
    }
    for (int e = tid; e < RAD_F * HID; e += THREADS) sW1[e] = W1[e];
    for (int e = tid; e < ANG_F * OUT_F; e += THREADS) sWa[e] = Wa[e];
    if (tid < HID)   sb1_[tid] = b1[tid];
    else if (tid < HID + OUT_F) sba_[tid - HID] = ba[tid - HID];
    __syncthreads();

    // ---- h = silu(radial@W1+b1) -> A tile (fp16) ----
    {
        const int j  = tid & 63;
        const int mb = tid >> 6;
#pragma unroll 4
        for (int s = 0; s < TILE_M / 4; s++) {
            const int m = mb + s * 4;
            float a = sb1_[j];
#pragma unroll
            for (int r = 0; r < RAD_F; r++)
                a = fmaf(srad[m * 33 + r], sW1[r * HID + j], a);
            *(__half*)(smem + SM_A + m * APITCH + j * 2) =
                __float2half_rn(silu_tanh(a));
        }
    }
    __syncthreads();   // A complete; radial fully consumed

    // ---- warp decomposition (validated R9-R14) ----
    const int mpair = warp >> 1;
    const int nhalf = warp & 1;
    const int m0    = mpair * 32;
    const int nc0   = nhalf * 32;

    const uint32_t a_row  = ((lane >> 3) & 1) * 8 + (lane & 7);
    const uint32_t a_kadd = (lane >> 4) * 16;
    const int r0 = lane >> 2;

    // ---- load A (h) fragments; write f fp16 tile over radial ----
    uint32_t Ah0[4][4], Ah1[4][4];
    {
        const uint32_t base0 = sb + SM_A + (m0 + a_row) * APITCH + a_kadd;
        const uint32_t base1 = base0 + 16 * APITCH;
#pragma unroll
        for (int ks = 0; ks < 4; ks++) ldsm_x4(Ah0[ks], base0 + ks * 32);
#pragma unroll
        for (int ks = 0; ks < 4; ks++) ldsm_x4(Ah1[ks], base1 + ks * 32);
    }
    for (int e = tid; e < TILE_M * IN_F; e += THREADS) {
        const int m = e >> 6, c = e & 63;
        const float v = features[(size_t)(n0 + m) * IN_F + c];
        *(__half*)(smem + SM_F + m * APITCH + c * 2) = __float2half_rn(v);
    }
    __syncthreads();   // all warps have A frags; F tile visible

    float acc0[4][4], acc1[4][4];
#pragma unroll
    for (int nt = 0; nt < 4; nt++)
#pragma unroll
        for (int j = 0; j < 4; j++) { acc0[nt][j] = 0.0f; acc1[nt][j] = 0.0f; }

    const uint32_t fa0 = sb + SM_F + (m0 + r0) * APITCH;   // band0 row r0
    const uint32_t fa1 = fa0 + 8 * APITCH;
    const uint32_t fa2 = fa0 + 16 * APITCH;
    const uint32_t fa3 = fa0 + 24 * APITCH;

    // per-warp/lane base into the fragment stream
    const uint8_t* bw = g_streamR + (size_t)nhalf * 4096 + (uint32_t)lane * 16;
    // per-warp prefetch base: lane covers its own 128B line of a slot region
    const uint8_t* pw = g_streamR + (size_t)nhalf * 4096 + (uint32_t)lane * 128;

    // warm slots 0 and 1, prime the register pipeline (slot 0, ks 0)
    prefetch_l1(pw);
    prefetch_l1(pw + 8192);
    uint4 cA = __ldg((const uint4*)(bw));
    uint4 cB = __ldg((const uint4*)(bw + 512));

    // ---- mainloop: 64 slots; dist-1 reg pipeline + dist-2 L1 prefetch ----
    for (int jp = 0; jp < 32; jp++) {
        const uint32_t v0 = lds32(fa0 + jp * 4);
        const uint32_t v1 = lds32(fa1 + jp * 4);
        const uint32_t v2 = lds32(fa2 + jp * 4);
        const uint32_t v3 = lds32(fa3 + jp * 4);

#pragma unroll
        for (int half = 0; half < 2; half++) {
            const int i = jp * 2 + half;
            const uint8_t* sbase = bw + (size_t)i * 8192;

            // warm slot i+2 (whole 4KB region, one line per lane); slots
            // 64/65 exist (b2 + padding) so i+2 <= 65 is always in-bounds
            prefetch_l1(pw + (size_t)(i + 2) * 8192);

            const uint32_t sel = half ? 0x3232u : 0x1010u;
            const uint32_t f0 = __byte_perm(v0, v0, sel);
            const uint32_t f1 = __byte_perm(v1, v1, sel);
            const uint32_t f2 = __byte_perm(v2, v2, sel);
            const uint32_t f3 = __byte_perm(v3, v3, sel);

#pragma unroll
            for (int ks = 0; ks < 4; ks++) {
                // register prefetch of next ks-step (next slot at ks==3;
                // slot 64 = b2 is contiguous after 63, priming the bias pass)
                const uint8_t* nbase = (ks < 3) ? (sbase + (ks + 1) * 1024)
                                                : (sbase + 8192);
                const uint4 nA = __ldg((const uint4*)(nbase));
                const uint4 nB = __ldg((const uint4*)(nbase + 512));

                // A frag regs {0,2} = row r0, {1,3} = row r0+8
                uint32_t As0[4], As1[4];
                As0[0] = hmul2u(Ah0[ks][0], f0);
                As0[1] = hmul2u(Ah0[ks][1], f1);
                As0[2] = hmul2u(Ah0[ks][2], f0);
                As0[3] = hmul2u(Ah0[ks][3], f1);
                As1[0] = hmul2u(Ah1[ks][0], f2);
                As1[1] = hmul2u(Ah1[ks][1], f3);
                As1[2] = hmul2u(Ah1[ks][2], f2);
                As1[3] = hmul2u(Ah1[ks][3], f3);

                mma_f16(acc0[0], As0, cA.x, cA.y);
                mma_f16(acc1[0], As1, cA.x, cA.y);
                mma_f16(acc0[1], As0, cA.z, cA.w);
                mma_f16(acc1[1], As1, cA.z, cA.w);
                mma_f16(acc0[2], As0, cB.x, cB.y);
                mma_f16(acc1[2], As1, cB.x, cB.y);
                mma_f16(acc0[3], As0, cB.z, cB.w);
                mma_f16(acc1[3], As1, cB.z, cB.w);

                cA = nA; cB = nB;
            }
        }
    }

    // ---- b2 pass: slot 64 (cA/cB already hold ks=0 via prefetch) ----
    {
        uint32_t Fh0[4], Fh1[4];
        const uint32_t base0 = sb + SM_F + (m0 + a_row) * APITCH + a_kadd;
        const uint32_t base1 = base0 + 16 * APITCH;
        const uint8_t* sbase = bw + (size_t)64 * 8192;
#pragma unroll
        for (int ks = 0; ks < 4; ks++) {
            uint4 nA, nB;
            if (ks < 3) {
                nA = __ldg((const uint4*)(sbase + (ks + 1) * 1024));
                nB = __ldg((const uint4*)(sbase + (ks + 1) * 1024 + 512));
            } else {
                nA = cA; nB = cB;
            }
            ldsm_x4(Fh0, base0 + ks * 32);
            ldsm_x4(Fh1, base1 + ks * 32);
            mma_f16(acc0[0], Fh0, cA.x, cA.y);
            mma_f16(acc1[0], Fh1, cA.x, cA.y);
            mma_f16(acc0[1], Fh0, cA.z, cA.w);
            mma_f16(acc1[1], Fh1, cA.z, cA.w);
            mma_f16(acc0[2], Fh0, cB.x, cB.y);
            mma_f16(acc1[2], Fh1, cB.x, cB.y);
            mma_f16(acc0[3], Fh0, cB.z, cB.w);
            mma_f16(acc1[3], Fh1, cB.z, cB.w);
            cA = nA; cB = nB;
        }
    }

    // ---- epilogue: ang = angular@Wa+ba (angular from gmem), mult, store ----
    const int gc = (lane & 3) * 2;
#pragma unroll
    for (int band = 0; band < 2; band++) {
        float (*ac)[4] = band ? acc1 : acc0;
#pragma unroll
        for (int rs = 0; rs < 2; rs++) {
            const int m = m0 + band * 16 + rs * 8 + r0;
            float sa[16];
            {
                const float4* ap = (const float4*)(angular + (size_t)(n0 + m) * ANG_F);
#pragma unroll
                for (int q4 = 0; q4 < 4; q4++) {
                    float4 v = __ldg(ap + q4);
                    sa[q4 * 4 + 0] = v.x; sa[q4 * 4 + 1] = v.y;
                    sa[q4 * 4 + 2] = v.z; sa[q4 * 4 + 3] = v.w;
                }
            }
            const size_t orow = (size_t)(n0 + m) * OUT_F;
#pragma unroll
            for (int nt = 0; nt < 4; nt++) {
                const int c0 = nc0 + nt * 8 + gc;
                float a0 = sba_[c0], a1 = sba_[c0 + 1];
#pragma unroll
                for (int q = 0; q < 16; q++) {
                    a0 = fmaf(sa[q], sWa[q * 64 + c0], a0);
                    a1 = fmaf(sa[q], sWa[q * 64 + c0 + 1], a1);
                }
                float2 o;
                o.x = ac[nt][rs * 2 + 0] * a0;
                o.y = ac[nt][rs * 2 + 1] * a1;
                *(float2*)(out + orow + c0) = o;
            }
        }
    }
}

// ---------------------------------------------------------------------------
// Launch
// ---------------------------------------------------------------------------
extern "C" void kernel_launch(void* const* d_in, const int* in_sizes, int n_in,
                              void* d_out, int out_size)
{
    const float* features = (const float*)d_in[0];
    const float* radial   = (const float*)d_in[1];
    const float* angular  = (const float*)d_in[2];
    const float* W1       = (const float*)d_in[3];
    const float* b1       = (const float*)d_in[4];
    const float* W2       = (const float*)d_in[5];
    const float* b2       = (const float*)d_in[6];
    const float* Wa       = (const float*)d_in[7];
    const float* ba       = (const float*)d_in[8];
    float* out = (float*)d_out;
    (void)in_sizes; (void)n_in; (void)out_size;

    cudaFuncSetAttribute(tp_main, cudaFuncAttributeMaxDynamicSharedMemorySize, SMEM_BYTES);

    tp_wsplit<<<(64 * 4096 + 4096 + THREADS - 1) / THREADS, THREADS>>>(W2, b2);
    tp_main<<<NTILES, THREADS, SMEM_BYTES>>>(features, radial, angular,
                                             W1, b1, Wa, ba, out);
}

// round 16
// speedup vs baseline: 1.1673x; 1.1673x over previous
#include <cuda_runtime.h>
#include <cuda_fp16.h>
#include <math.h>
#include <stdint.h>

#define NTOK  65536
#define IN_F  64
#define OUT_F 64
#define RAD_F 32
#define ANG_F 16
#define HID   64

#define TILE_M   128
#define NTILES   (NTOK / TILE_M)   // 512
#define THREADS  256

#define APITCH   144               // fp16 tile pitch (ldsm conflict-free)

// ---------------------------------------------------------------------------
// B stream in FRAGMENT order (validated R13/R14):
// addr(slot, nh, ks, row16, lane, j, byte) =
//   (slot*2+nh)*4096 + (ks*2+row16)*512 + lane*16 + j*4 + byte*2
// Slots 0..63 = W2_i, slot 64 = b2, slot 65 = padding.
// ---------------------------------------------------------------------------
__device__ __align__(1024) uint8_t g_streamR[(size_t)66 * 8192];

__device__ __forceinline__ void store_frag(int slot, int o, int k, __half v) {
    const int nh    = o >> 5;
    const int ol    = o & 31;
    const int row16 = ol >> 4;
    const int oo    = ol & 15;
    const int ks    = k >> 4;
    const int kl    = k & 15;
    const int j     = (oo >> 3) * 2 + (kl >> 3);
    const int lane  = (oo & 7) * 4 + ((kl & 7) >> 1);
    const int byte  = kl & 1;
    const size_t addr = (size_t)(slot * 2 + nh) * 4096
                      + (size_t)(ks * 2 + row16) * 512
                      + (size_t)lane * 16 + j * 4 + byte * 2;
    *(__half*)(g_streamR + addr) = v;
}

__global__ void tp_wsplit(const float* __restrict__ W2, const float* __restrict__ b2)
{
    const int idx = blockIdx.x * THREADS + threadIdx.x;
    if (idx < 64 * 4096) {
        const int k  = idx >> 12;
        const int io = idx & 4095;
        const int o  = io & 63;
        const int i  = io >> 6;
        store_frag(i, o, k, __float2half_rn(W2[idx]));
    } else if (idx < 64 * 4096 + 4096) {
        const int e = idx - 64 * 4096;
        const int i = e >> 6;     // contraction dim of the b2 pass
        const int o = e & 63;
        store_frag(64, o, i, __float2half_rn(b2[e]));
    }
}

// ---------------------------------------------------------------------------
// PTX helpers
// ---------------------------------------------------------------------------
__device__ __forceinline__ void ldsm_x4(uint32_t* r, uint32_t addr) {
    asm volatile("ldmatrix.sync.aligned.m8n8.x4.shared.b16 {%0,%1,%2,%3}, [%4];"
        : "=r"(r[0]), "=r"(r[1]), "=r"(r[2]), "=r"(r[3]) : "r"(addr));
}
__device__ __forceinline__ void mma_f16(float* d, const uint32_t* a,
                                        uint32_t b0, uint32_t b1) {
    asm volatile(
        "mma.sync.aligned.m16n8k16.row.col.f32.f16.f16.f32 "
        "{%0,%1,%2,%3}, {%4,%5,%6,%7}, {%8,%9}, {%0,%1,%2,%3};"
        : "+f"(d[0]), "+f"(d[1]), "+f"(d[2]), "+f"(d[3])
        : "r"(a[0]), "r"(a[1]), "r"(a[2]), "r"(a[3]), "r"(b0), "r"(b1));
}
__device__ __forceinline__ uint32_t hmul2u(uint32_t a, uint32_t f) {
    uint32_t d;
    asm("mul.rn.f16x2 %0, %1, %2;" : "=r"(d) : "r"(a), "r"(f));
    return d;
}
__device__ __forceinline__ uint32_t lds32(uint32_t addr) {
    uint32_t v;
    asm volatile("ld.shared.b32 %0, [%1];" : "=r"(v) : "r"(addr));
    return v;
}
__device__ __forceinline__ float silu_tanh(float x) {
    float t;
    asm("tanh.approx.f32 %0, %1;" : "=f"(t) : "f"(0.5f * x));
    const float hx = 0.5f * x;
    return fmaf(hx, t, hx);
}

// ---------------------------------------------------------------------------
// SMEM layout (bytes) — 49664 total
// ---------------------------------------------------------------------------
#define SM_A    0u        // h fp16 tile 128 rows          (18432)
#define SM_F    18432u    // radial staging, then f fp16   (18432)
#define SM_W1   36864u    // W1 fp32 [32][64]              (8192)
#define SM_WA   45056u    // Wa fp32 [16][64]              (4096)
#define SM_B1   49152u    // b1 fp32 [64]                  (256)
#define SM_BA   49408u    // ba fp32 [64]                  (256)
#define SMEM_BYTES 49664

// ---------------------------------------------------------------------------
// Main kernel: 128 tokens/CTA, 8 warps, 2 CTAs/SM.
// Warp = (m-pair, n-half): 32 rows x 32 cols. B via LDG fragments with
// distance-1 register pipeline; sparse convergence barrier every 8 slots
// keeps all warps' B windows co-resident in L1.
// ---------------------------------------------------------------------------
__global__ __launch_bounds__(THREADS, 2)
void tp_main(const float* __restrict__ features,
             const float* __restrict__ radial,
             const float* __restrict__ angular,
             const float* __restrict__ W1,
             const float* __restrict__ b1,
             const float* __restrict__ Wa,
             const float* __restrict__ ba,
             float* __restrict__ out)
{
    extern __shared__ __align__(1024) uint8_t smem[];
    const uint32_t sb = (uint32_t)__cvta_generic_to_shared(smem);
    const int tid  = threadIdx.x;
    const int lane = tid & 31;
    const int warp = tid >> 5;
    const int n0   = blockIdx.x * TILE_M;

    // ---- stage radial (into SM_F region) + weights ----
    float* srad = (float*)(smem + SM_F);     // [128][33]
    float* sW1  = (float*)(smem + SM_W1);
    float* sWa  = (float*)(smem + SM_WA);
    float* sb1_ = (float*)(smem + SM_B1);
    float* sba_ = (float*)(smem + SM_BA);

    for (int e = tid; e < TILE_M * RAD_F; e += THREADS) {
        const int m = e >> 5, r = e & 31;
        srad[m * 33 + r] = radial[(size_t)(n0 + m) * RAD_F + r];
    }
    for (int e = tid; e < RAD_F * HID; e += THREADS) sW1[e] = W1[e];
    for (int e = tid; e < ANG_F * OUT_F; e += THREADS) sWa[e] = Wa[e];
    if (tid < HID)   sb1_[tid] = b1[tid];
    else if (tid < HID + OUT_F) sba_[tid - HID] = ba[tid - HID];
    __syncthreads();

    // ---- h = silu(radial@W1+b1) -> A tile (fp16) ----
    {
        const int j  = tid & 63;
        const int mb = tid >> 6;
#pragma unroll 4
        for (int s = 0; s < TILE_M / 4; s++) {
            const int m = mb + s * 4;
            float a = sb1_[j];
#pragma unroll
            for (int r = 0; r < RAD_F; r++)
                a = fmaf(srad[m * 33 + r], sW1[r * HID + j], a);
            *(__half*)(smem + SM_A + m * APITCH + j * 2) =
                __float2half_rn(silu_tanh(a));
        }
    }
    __syncthreads();   // A complete; radial fully consumed

    // ---- warp decomposition (validated R9-R14) ----
    const int mpair = warp >> 1;
    const int nhalf = warp & 1;
    const int m0    = mpair * 32;
    const int nc0   = nhalf * 32;

    const uint32_t a_row  = ((lane >> 3) & 1) * 8 + (lane & 7);
    const uint32_t a_kadd = (lane >> 4) * 16;
    const int r0 = lane >> 2;

    // ---- load A (h) fragments; write f fp16 tile over radial ----
    uint32_t Ah0[4][4], Ah1[4][4];
    {
        const uint32_t base0 = sb + SM_A + (m0 + a_row) * APITCH + a_kadd;
        const uint32_t base1 = base0 + 16 * APITCH;
#pragma unroll
        for (int ks = 0; ks < 4; ks++) ldsm_x4(Ah0[ks], base0 + ks * 32);
#pragma unroll
        for (int ks = 0; ks < 4; ks++) ldsm_x4(Ah1[ks], base1 + ks * 32);
    }
    for (int e = tid; e < TILE_M * IN_F; e += THREADS) {
        const int m = e >> 6, c = e & 63;
        const float v = features[(size_t)(n0 + m) * IN_F + c];
        *(__half*)(smem + SM_F + m * APITCH + c * 2) = __float2half_rn(v);
    }
    __syncthreads();   // all warps have A frags; F tile visible

    float acc0[4][4], acc1[4][4];
#pragma unroll
    for (int nt = 0; nt < 4; nt++)
#pragma unroll
        for (int j = 0; j < 4; j++) { acc0[nt][j] = 0.0f; acc1[nt][j] = 0.0f; }

    const uint32_t fa0 = sb + SM_F + (m0 + r0) * APITCH;   // band0 row r0
    const uint32_t fa1 = fa0 + 8 * APITCH;
    const uint32_t fa2 = fa0 + 16 * APITCH;
    const uint32_t fa3 = fa0 + 24 * APITCH;

    // per-warp/lane base into the fragment stream
    const uint8_t* bw = g_streamR + (size_t)nhalf * 4096 + (uint32_t)lane * 16;

    // prime the pipeline: slot 0, ks 0
    uint4 cA = __ldg((const uint4*)(bw));
    uint4 cB = __ldg((const uint4*)(bw + 512));

    // ---- mainloop: 64 slots; dist-1 prefetch; convergence barrier /8 slots ----
    for (int jp = 0; jp < 32; jp++) {
        // re-converge all warps so their B windows stay co-resident in L1
        if ((jp & 3) == 0) __syncthreads();

        const uint32_t v0 = lds32(fa0 + jp * 4);
        const uint32_t v1 = lds32(fa1 + jp * 4);
        const uint32_t v2 = lds32(fa2 + jp * 4);
        const uint32_t v3 = lds32(fa3 + jp * 4);

#pragma unroll
        for (int half = 0; half < 2; half++) {
            const int i = jp * 2 + half;
            const uint8_t* sbase = bw + (size_t)i * 8192;

            const uint32_t sel = half ? 0x3232u : 0x1010u;
            const uint32_t f0 = __byte_perm(v0, v0, sel);
            const uint32_t f1 = __byte_perm(v1, v1, sel);
            const uint32_t f2 = __byte_perm(v2, v2, sel);
            const uint32_t f3 = __byte_perm(v3, v3, sel);

#pragma unroll
            for (int ks = 0; ks < 4; ks++) {
                // register prefetch of next ks-step (next slot at ks==3;
                // slot 64 = b2 is contiguous after 63, priming the bias pass)
                const uint8_t* nbase = (ks < 3) ? (sbase + (ks + 1) * 1024)
                                                : (sbase + 8192);
                const uint4 nA = __ldg((const uint4*)(nbase));
                const uint4 nB = __ldg((const uint4*)(nbase + 512));

                // A frag regs {0,2} = row r0, {1,3} = row r0+8
                uint32_t As0[4], As1[4];
                As0[0] = hmul2u(Ah0[ks][0], f0);
                As0[1] = hmul2u(Ah0[ks][1], f1);
                As0[2] = hmul2u(Ah0[ks][2], f0);
                As0[3] = hmul2u(Ah0[ks][3], f1);
                As1[0] = hmul2u(Ah1[ks][0], f2);
                As1[1] = hmul2u(Ah1[ks][1], f3);
                As1[2] = hmul2u(Ah1[ks][2], f2);
                As1[3] = hmul2u(Ah1[ks][3], f3);

                mma_f16(acc0[0], As0, cA.x, cA.y);
                mma_f16(acc1[0], As1, cA.x, cA.y);
                mma_f16(acc0[1], As0, cA.z, cA.w);
                mma_f16(acc1[1], As1, cA.z, cA.w);
                mma_f16(acc0[2], As0, cB.x, cB.y);
                mma_f16(acc1[2], As1, cB.x, cB.y);
                mma_f16(acc0[3], As0, cB.z, cB.w);
                mma_f16(acc1[3], As1, cB.z, cB.w);

                cA = nA; cB = nB;
            }
        }
    }

    // ---- b2 pass: slot 64 (cA/cB already hold ks=0 via prefetch) ----
    {
        uint32_t Fh0[4], Fh1[4];
        const uint32_t base0 = sb + SM_F + (m0 + a_row) * APITCH + a_kadd;
        const uint32_t base1 = base0 + 16 * APITCH;
        const uint8_t* sbase = bw + (size_t)64 * 8192;
#pragma unroll
        for (int ks = 0; ks < 4; ks++) {
            uint4 nA, nB;
            if (ks < 3) {
                nA = __ldg((const uint4*)(sbase + (ks + 1) * 1024));
                nB = __ldg((const uint4*)(sbase + (ks + 1) * 1024 + 512));
            } else {
                nA = cA; nB = cB;
            }
            ldsm_x4(Fh0, base0 + ks * 32);
            ldsm_x4(Fh1, base1 + ks * 32);
            mma_f16(acc0[0], Fh0, cA.x, cA.y);
            mma_f16(acc1[0], Fh1, cA.x, cA.y);
            mma_f16(acc0[1], Fh0, cA.z, cA.w);
            mma_f16(acc1[1], Fh1, cA.z, cA.w);
            mma_f16(acc0[2], Fh0, cB.x, cB.y);
            mma_f16(acc1[2], Fh1, cB.x, cB.y);
            mma_f16(acc0[3], Fh0, cB.z, cB.w);
            mma_f16(acc1[3], Fh1, cB.z, cB.w);
            cA = nA; cB = nB;
        }
    }

    // ---- epilogue: ang = angular@Wa+ba (angular from gmem), mult, store ----
    const int gc = (lane & 3) * 2;
#pragma unroll
    for (int band = 0; band < 2; band++) {
        float (*ac)[4] = band ? acc1 : acc0;
#pragma unroll
        for (int rs = 0; rs < 2; rs++) {
            const int m = m0 + band * 16 + rs * 8 + r0;
            float sa[16];
            {
                const float4* ap = (const float4*)(angular + (size_t)(n0 + m) * ANG_F);
#pragma unroll
                for (int q4 = 0; q4 < 4; q4++) {
                    float4 v = __ldg(ap + q4);
                    sa[q4 * 4 + 0] = v.x; sa[q4 * 4 + 1] = v.y;
                    sa[q4 * 4 + 2] = v.z; sa[q4 * 4 + 3] = v.w;
                }
            }
            const size_t orow = (size_t)(n0 + m) * OUT_F;
#pragma unroll
            for (int nt = 0; nt < 4; nt++) {
                const int c0 = nc0 + nt * 8 + gc;
                float a0 = sba_[c0], a1 = sba_[c0 + 1];
#pragma unroll
                for (int q = 0; q < 16; q++) {
                    a0 = fmaf(sa[q], sWa[q * 64 + c0], a0);
                    a1 = fmaf(sa[q], sWa[q * 64 + c0 + 1], a1);
                }
                float2 o;
                o.x = ac[nt][rs * 2 + 0] * a0;
                o.y = ac[nt][rs * 2 + 1] * a1;
                *(float2*)(out + orow + c0) = o;
            }
        }
    }
}

// ---------------------------------------------------------------------------
// Launch
// ---------------------------------------------------------------------------
extern "C" void kernel_launch(void* const* d_in, const int* in_sizes, int n_in,
                              void* d_out, int out_size)
{
    const float* features = (const float*)d_in[0];
    const float* radial   = (const float*)d_in[1];
    const float* angular  = (const float*)d_in[2];
    const float* W1       = (const float*)d_in[3];
    const float* b1       = (const float*)d_in[4];
    const float* W2       = (const float*)d_in[5];
    const float* b2       = (const float*)d_in[6];
    const float* Wa       = (const float*)d_in[7];
    const float* ba       = (const float*)d_in[8];
    float* out = (float*)d_out;
    (void)in_sizes; (void)n_in; (void)out_size;

    cudaFuncSetAttribute(tp_main, cudaFuncAttributeMaxDynamicSharedMemorySize, SMEM_BYTES);

    tp_wsplit<<<(64 * 4096 + 4096 + THREADS - 1) / THREADS, THREADS>>>(W2, b2);
    tp_main<<<NTILES, THREADS, SMEM_BYTES>>>(features, radial, angular,
                                             W1, b1, Wa, ba, out);
}

// round 17
// speedup vs baseline: 1.2004x; 1.0284x over previous
#include <cuda_runtime.h>
#include <cuda_fp16.h>
#include <math.h>
#include <stdint.h>

#define NTOK  65536
#define IN_F  64
#define OUT_F 64
#define RAD_F 32
#define ANG_F 16
#define HID   64

#define TILE_M   32
#define NTILES   (NTOK / TILE_M)   // 2048
#define THREADS  128

#define APITCH   144               // fp16 tile pitch (ldsm conflict-free)

// ---------------------------------------------------------------------------
// B stream in FRAGMENT order (validated R13/R14):
// addr(slot, nh, ks, row16, lane, j, byte) =
//   (slot*2+nh)*4096 + (ks*2+row16)*512 + lane*16 + j*4 + byte*2
// Slots 0..63 = W2_i, slot 64 = b2, slot 65 = padding.
// ---------------------------------------------------------------------------
__device__ __align__(1024) uint8_t g_streamR[(size_t)66 * 8192];

__device__ __forceinline__ void store_frag(int slot, int o, int k, __half v) {
    const int nh    = o >> 5;
    const int ol    = o & 31;
    const int row16 = ol >> 4;
    const int oo    = ol & 15;
    const int ks    = k >> 4;
    const int kl    = k & 15;
    const int j     = (oo >> 3) * 2 + (kl >> 3);
    const int lane  = (oo & 7) * 4 + ((kl & 7) >> 1);
    const int byte  = kl & 1;
    const size_t addr = (size_t)(slot * 2 + nh) * 4096
                      + (size_t)(ks * 2 + row16) * 512
                      + (size_t)lane * 16 + j * 4 + byte * 2;
    *(__half*)(g_streamR + addr) = v;
}

__global__ void tp_wsplit(const float* __restrict__ W2, const float* __restrict__ b2)
{
    const int idx = blockIdx.x * 256 + threadIdx.x;
    if (idx < 64 * 4096) {
        const int k  = idx >> 12;
        const int io = idx & 4095;
        const int o  = io & 63;
        const int i  = io >> 6;
        store_frag(i, o, k, __float2half_rn(W2[idx]));
    } else if (idx < 64 * 4096 + 4096) {
        const int e = idx - 64 * 4096;
        const int i = e >> 6;     // contraction dim of the b2 pass
        const int o = e & 63;
        store_frag(64, o, i, __float2half_rn(b2[e]));
    }
}

// ---------------------------------------------------------------------------
// PTX helpers
// ---------------------------------------------------------------------------
__device__ __forceinline__ void ldsm_x4(uint32_t* r, uint32_t addr) {
    asm volatile("ldmatrix.sync.aligned.m8n8.x4.shared.b16 {%0,%1,%2,%3}, [%4];"
        : "=r"(r[0]), "=r"(r[1]), "=r"(r[2]), "=r"(r[3]) : "r"(addr));
}
__device__ __forceinline__ void mma_f16(float* d, const uint32_t* a,
                                        uint32_t b0, uint32_t b1) {
    asm volatile(
        "mma.sync.aligned.m16n8k16.row.col.f32.f16.f16.f32 "
        "{%0,%1,%2,%3}, {%4,%5,%6,%7}, {%8,%9}, {%0,%1,%2,%3};"
        : "+f"(d[0]), "+f"(d[1]), "+f"(d[2]), "+f"(d[3])
        : "r"(a[0]), "r"(a[1]), "r"(a[2]), "r"(a[3]), "r"(b0), "r"(b1));
}
__device__ __forceinline__ uint32_t hmul2u(uint32_t a, uint32_t f) {
    uint32_t d;
    asm("mul.rn.f16x2 %0, %1, %2;" : "=r"(d) : "r"(a), "r"(f));
    return d;
}
__device__ __forceinline__ uint32_t lds32(uint32_t addr) {
    uint32_t v;
    asm volatile("ld.shared.b32 %0, [%1];" : "=r"(v) : "r"(addr));
    return v;
}
__device__ __forceinline__ float silu_tanh(float x) {
    float t;
    asm("tanh.approx.f32 %0, %1;" : "=f"(t) : "f"(0.5f * x));
    const float hx = 0.5f * x;
    return fmaf(hx, t, hx);
}

// ---------------------------------------------------------------------------
// SMEM layout (bytes) — 22016 per CTA (6+ CTAs/SM)
// ---------------------------------------------------------------------------
#define SM_A    0u        // h fp16 tile 32 rows           (4608)
#define SM_F    4608u     // radial staging, then f fp16   (4608)
#define SM_W1   9216u     // W1 fp32 [32][64]              (8192)
#define SM_WA   17408u    // Wa fp32 [16][64]              (4096)
#define SM_B1   21504u    // b1 fp32 [64]                  (256)
#define SM_BA   21760u    // ba fp32 [64]                  (256)
#define SMEM_BYTES 22016

// ---------------------------------------------------------------------------
// Main kernel: 32 tokens/CTA, 4 warps, ~6 CTAs/SM (85-reg budget).
// Warp = (mband, nhalf): 16 rows x 32 cols. B via LDG fragments with
// distance-1 register pipeline; barrier-free mainloop.
// ---------------------------------------------------------------------------
__global__ __launch_bounds__(THREADS, 6)
void tp_main(const float* __restrict__ features,
             const float* __restrict__ radial,
             const float* __restrict__ angular,
             const float* __restrict__ W1,
             const float* __restrict__ b1,
             const float* __restrict__ Wa,
             const float* __restrict__ ba,
             float* __restrict__ out)
{
    extern __shared__ __align__(1024) uint8_t smem[];
    const uint32_t sb = (uint32_t)__cvta_generic_to_shared(smem);
    const int tid  = threadIdx.x;
    const int lane = tid & 31;
    const int warp = tid >> 5;
    const int n0   = blockIdx.x * TILE_M;

    // ---- stage radial (into SM_F region) + weights ----
    float* srad = (float*)(smem + SM_F);     // [32][33]
    float* sW1  = (float*)(smem + SM_W1);
    float* sWa  = (float*)(smem + SM_WA);
    float* sb1_ = (float*)(smem + SM_B1);
    float* sba_ = (float*)(smem + SM_BA);

    for (int e = tid; e < TILE_M * RAD_F; e += THREADS) {
        const int m = e >> 5, r = e & 31;
        srad[m * 33 + r] = radial[(size_t)(n0 + m) * RAD_F + r];
    }
    for (int e = tid; e < RAD_F * HID; e += THREADS) sW1[e] = W1[e];
    for (int e = tid; e < ANG_F * OUT_F; e += THREADS) sWa[e] = Wa[e];
    if (tid < HID) sb1_[tid] = b1[tid];
    else           sba_[tid - HID] = ba[tid - HID];
    __syncthreads();

    // ---- h = silu(radial@W1+b1) -> A tile (fp16) ----
    {
        const int j  = tid & 63;
        const int mb = tid >> 6;   // 0..1
#pragma unroll 4
        for (int s = 0; s < TILE_M / 2; s++) {
            const int m = mb + s * 2;
            float a = sb1_[j];
#pragma unroll
            for (int r = 0; r < RAD_F; r++)
                a = fmaf(srad[m * 33 + r], sW1[r * HID + j], a);
            *(__half*)(smem + SM_A + m * APITCH + j * 2) =
                __float2half_rn(silu_tanh(a));
        }
    }
    __syncthreads();   // A complete; radial fully consumed

    // ---- warp decomposition: 4 warps = 2 mbands x 2 nhalf ----
    const int mband = warp >> 1;          // 0..1 -> rows mband*16..+15
    const int nhalf = warp & 1;           // 0..1 -> cols nhalf*32..+31
    const int m0    = mband * 16;
    const int nc0   = nhalf * 32;

    const uint32_t a_row  = ((lane >> 3) & 1) * 8 + (lane & 7);
    const uint32_t a_kadd = (lane >> 4) * 16;
    const int r0 = lane >> 2;

    // ---- load A (h) fragments; write f fp16 tile over radial ----
    uint32_t Ah[4][4];
    {
        const uint32_t base = sb + SM_A + (m0 + a_row) * APITCH + a_kadd;
#pragma unroll
        for (int ks = 0; ks < 4; ks++) ldsm_x4(Ah[ks], base + ks * 32);
    }
    for (int e = tid; e < TILE_M * IN_F; e += THREADS) {
        const int m = e >> 6, c = e & 63;
        const float v = features[(size_t)(n0 + m) * IN_F + c];
        *(__half*)(smem + SM_F + m * APITCH + c * 2) = __float2half_rn(v);
    }
    __syncthreads();   // all warps have A frags; F tile visible

    float acc[4][4];
#pragma unroll
    for (int nt = 0; nt < 4; nt++)
#pragma unroll
        for (int j = 0; j < 4; j++) acc[nt][j] = 0.0f;

    const uint32_t fa0 = sb + SM_F + (m0 + r0) * APITCH;   // row r0
    const uint32_t fa1 = fa0 + 8 * APITCH;                 // row r0+8

    // per-warp/lane base into the fragment stream
    const uint8_t* bw = g_streamR + (size_t)nhalf * 4096 + (uint32_t)lane * 16;

    // prime the pipeline: slot 0, ks 0
    uint4 cA = __ldg((const uint4*)(bw));
    uint4 cB = __ldg((const uint4*)(bw + 512));

    // ---- mainloop: 64 slots; dist-1 prefetch; NO barriers ----
    for (int jp = 0; jp < 32; jp++) {
        const uint32_t v0 = lds32(fa0 + jp * 4);
        const uint32_t v1 = lds32(fa1 + jp * 4);

#pragma unroll
        for (int half = 0; half < 2; half++) {
            const int i = jp * 2 + half;
            const uint8_t* sbase = bw + (size_t)i * 8192;

            const uint32_t sel = half ? 0x3232u : 0x1010u;
            const uint32_t f0 = __byte_perm(v0, v0, sel);
            const uint32_t f1 = __byte_perm(v1, v1, sel);

#pragma unroll
            for (int ks = 0; ks < 4; ks++) {
                // register prefetch of next ks-step (next slot at ks==3;
                // slot 64 = b2 is contiguous after 63, priming the bias pass)
                const uint8_t* nbase = (ks < 3) ? (sbase + (ks + 1) * 1024)
                                                : (sbase + 8192);
                const uint4 nA = __ldg((const uint4*)(nbase));
                const uint4 nB = __ldg((const uint4*)(nbase + 512));

                // A frag regs {0,2} = row r0, {1,3} = row r0+8
                uint32_t As[4];
                As[0] = hmul2u(Ah[ks][0], f0);
                As[1] = hmul2u(Ah[ks][1], f1);
                As[2] = hmul2u(Ah[ks][2], f0);
                As[3] = hmul2u(Ah[ks][3], f1);

                mma_f16(acc[0], As, cA.x, cA.y);
                mma_f16(acc[1], As, cA.z, cA.w);
                mma_f16(acc[2], As, cB.x, cB.y);
                mma_f16(acc[3], As, cB.z, cB.w);

                cA = nA; cB = nB;
            }
        }
    }

    // ---- b2 pass: slot 64 (cA/cB already hold ks=0 via prefetch) ----
    {
        uint32_t Fh[4];
        const uint32_t base = sb + SM_F + (m0 + a_row) * APITCH + a_kadd;
        const uint8_t* sbase = bw + (size_t)64 * 8192;
#pragma unroll
        for (int ks = 0; ks < 4; ks++) {
            uint4 nA, nB;
            if (ks < 3) {
                nA = __ldg((const uint4*)(sbase + (ks + 1) * 1024));
                nB = __ldg((const uint4*)(sbase + (ks + 1) * 1024 + 512));
            } else {
                nA = cA; nB = cB;
            }
            ldsm_x4(Fh, base + ks * 32);
            mma_f16(acc[0], Fh, cA.x, cA.y);
            mma_f16(acc[1], Fh, cA.z, cA.w);
            mma_f16(acc[2], Fh, cB.x, cB.y);
            mma_f16(acc[3], Fh, cB.z, cB.w);
            cA = nA; cB = nB;
        }
    }

    // ---- epilogue: ang = angular@Wa+ba (angular from gmem), mult, store ----
    const int gc = (lane & 3) * 2;
#pragma unroll
    for (int rs = 0; rs < 2; rs++) {      // D frag: {0,1}=row r0, {2,3}=row r0+8
        const int m = m0 + rs * 8 + r0;
        float sa[16];
        {
            const float4* ap = (const float4*)(angular + (size_t)(n0 + m) * ANG_F);
#pragma unroll
            for (int q4 = 0; q4 < 4; q4++) {
                float4 v = __ldg(ap + q4);
                sa[q4 * 4 + 0] = v.x; sa[q4 * 4 + 1] = v.y;
                sa[q4 * 4 + 2] = v.z; sa[q4 * 4 + 3] = v.w;
            }
        }
        const size_t orow = (size_t)(n0 + m) * OUT_F;
#pragma unroll
        for (int nt = 0; nt < 4; nt++) {
            const int c0 = nc0 + nt * 8 + gc;
            float a0 = sba_[c0], a1 = sba_[c0 + 1];
#pragma unroll
            for (int q = 0; q < 16; q++) {
                a0 = fmaf(sa[q], sWa[q * 64 + c0], a0);
                a1 = fmaf(sa[q], sWa[q * 64 + c0 + 1], a1);
            }
            float2 o;
            o.x = acc[nt][rs * 2 + 0] * a0;
            o.y = acc[nt][rs * 2 + 1] * a1;
            *(float2*)(out + orow + c0) = o;
        }
    }
}

// ---------------------------------------------------------------------------
// Launch
// ---------------------------------------------------------------------------
extern "C" void kernel_launch(void* const* d_in, const int* in_sizes, int n_in,
                              void* d_out, int out_size)
{
    const float* features = (const float*)d_in[0];
    const float* radial   = (const float*)d_in[1];
    const float* angular  = (const float*)d_in[2];
    const float* W1       = (const float*)d_in[3];
    const float* b1       = (const float*)d_in[4];
    const float* W2       = (const float*)d_in[5];
    const float* b2       = (const float*)d_in[6];
    const float* Wa       = (const float*)d_in[7];
    const float* ba       = (const float*)d_in[8];
    float* out = (float*)d_out;
    (void)in_sizes; (void)n_in; (void)out_size;

    cudaFuncSetAttribute(tp_main, cudaFuncAttributeMaxDynamicSharedMemorySize, SMEM_BYTES);

    tp_wsplit<<<(64 * 4096 + 4096 + 255) / 256, 256>>>(W2, b2);
    tp_main<<<NTILES, THREADS, SMEM_BYTES>>>(features, radial, angular,
                                             W1, b1, Wa, ba, out);
}